// round 7
// baseline (speedup 1.0000x reference)
#include <cuda_runtime.h>
#include <cstdint>

// ---------------------------------------------------------------------------
// LGNN GINE layer, algebraically collapsed + linearity-split tf32 MMA MLP.
//   lgX  = 0.5*(x[col0]+x[col1])                          (stored tf32-rounded)
//   2x:  S[v]  = sum_{i: col1[i]==v, col0[i]!=col1[i]} relu(lgX[i]+x[v])
//        SW1   = tf32(S) @ W1                             (separate small GEMM)
//        lgX   = relu(lgX@W1 + SW1[col0] + b1) @ W2 + b2
//   out  = x + relu( segment_mean(lgX, col1) )
// k_mlp: persistent, 4 independent warp-pairs, 32-row tiles, cp.async staging.
// Epilogues routed acc -> smem -> row-major 128-bit global phase (LSU floor).
// ---------------------------------------------------------------------------

#define DD   128
#define DV   32
#define MAXE 200000
#define MAXN 50000
#define TILE 32

__device__ float g_S0[(size_t)MAXN * DD];
__device__ float g_S1[(size_t)MAXN * DD];
__device__ float g_Sf[(size_t)MAXN * DD];
__device__ float g_SW1[(size_t)MAXN * DD];
__device__ float g_lgX[(size_t)MAXE * DD];
__device__ float g_cnt[MAXN];
__device__ float g_Wr1[DD * DD];   // W1 tf32-rounded, [k][n]
__device__ float g_Wr2[DD * DD];

// ----------------------------- helpers --------------------------------------
__device__ __forceinline__ uint32_t smem_u32(const void* p) {
    uint32_t a;
    asm("{ .reg .u64 t; cvta.to.shared.u64 t, %1; cvt.u32.u64 %0, t; }"
        : "=r"(a) : "l"(p));
    return a;
}
__device__ __forceinline__ float tf32r(float f) {
    uint32_t u;
    asm("cvt.rna.tf32.f32 %0, %1;" : "=r"(u) : "f"(f));
    return __uint_as_float(u);
}
__device__ __forceinline__ void red_add_v4(float* p, float4 v) {
    asm volatile("red.global.add.v4.f32 [%0], {%1,%2,%3,%4};"
                 :: "l"(p), "f"(v.x), "f"(v.y), "f"(v.z), "f"(v.w) : "memory");
}
__device__ __forceinline__ void mma_tf32(float* d, const uint32_t* a,
                                         const uint32_t* b) {
    asm volatile(
        "mma.sync.aligned.m16n8k8.row.col.f32.tf32.tf32.f32 "
        "{%0,%1,%2,%3}, {%4,%5,%6,%7}, {%8,%9}, {%0,%1,%2,%3};"
        : "+f"(d[0]), "+f"(d[1]), "+f"(d[2]), "+f"(d[3])
        : "r"(a[0]), "r"(a[1]), "r"(a[2]), "r"(a[3]), "r"(b[0]), "r"(b[1]));
}
__device__ __forceinline__ void cp_async16(uint32_t dst, const void* src) {
    asm volatile("cp.async.cg.shared.global [%0], [%1], 16;"
                 :: "r"(dst), "l"(src) : "memory");
}
#define CP_COMMIT() asm volatile("cp.async.commit_group;" ::: "memory")
#define CP_WAIT0()  asm volatile("cp.async.wait_group 0;"  ::: "memory")
#define BAR(id)     asm volatile("bar.sync %0, 64;" :: "r"(id) : "memory")

#define LDA 132
#define LDW 136

// GEMM fragment body: acc[2][8][4] += A(rows R0.., k) * W(k, wn*64..)
#define GEMM_BODY(UW, UA, R0)                                                  \
    _Pragma("unroll")                                                          \
    for (int kk = 0; kk < 16; kk++) {                                          \
        uint32_t a[2][4], b[8][2];                                             \
        _Pragma("unroll")                                                      \
        for (int m = 0; m < 2; m++) {                                          \
            int rb = (R0) + 16 * m;                                            \
            a[m][0] = (UA)[(rb + ty) * LDA + kk * 8 + tx4];                    \
            a[m][1] = (UA)[(rb + ty + 8) * LDA + kk * 8 + tx4];                \
            a[m][2] = (UA)[(rb + ty) * LDA + kk * 8 + tx4 + 4];                \
            a[m][3] = (UA)[(rb + ty + 8) * LDA + kk * 8 + tx4 + 4];            \
        }                                                                      \
        _Pragma("unroll")                                                      \
        for (int n = 0; n < 8; n++) {                                          \
            int cc = wn * 64 + 8 * n + ty;                                     \
            b[n][0] = (UW)[(kk * 8 + tx4) * LDW + cc];                         \
            b[n][1] = (UW)[(kk * 8 + tx4 + 4) * LDW + cc];                     \
        }                                                                      \
        _Pragma("unroll")                                                      \
        for (int m = 0; m < 2; m++)                                            \
            _Pragma("unroll")                                                  \
            for (int n = 0; n < 8; n++)                                        \
                mma_tf32(acc[m][n], a[m], b[n]);                               \
    }

// store acc fragments into sA (row-major O tile), float2 per (m,n,row)
#define ACC_TO_SMEM(SA)                                                        \
    _Pragma("unroll")                                                          \
    for (int m = 0; m < 2; m++) {                                              \
        int rb = 16 * m + ty;                                                  \
        _Pragma("unroll")                                                      \
        for (int n = 0; n < 8; n++) {                                          \
            int cc = wn * 64 + 8 * n + 2 * tx4;                                \
            *(float2*)&(SA)[rb * LDA + cc] =                                   \
                make_float2(acc[m][n][0], acc[m][n][1]);                       \
            *(float2*)&(SA)[(rb + 8) * LDA + cc] =                             \
                make_float2(acc[m][n][2], acc[m][n][3]);                       \
        }                                                                      \
    }

#define ZERO_ACC()                                                             \
    _Pragma("unroll")                                                          \
    for (int m = 0; m < 2; m++)                                                \
        _Pragma("unroll")                                                      \
        for (int n = 0; n < 8; n++)                                            \
            _Pragma("unroll")                                                  \
            for (int j = 0; j < 4; j++) acc[m][n][j] = 0.f;

// ------------------- zero scratch + weight rounding --------------------------
__global__ void k_zero(float4* s0, float4* s1, float4* sf, float* cnt,
                       int n4, int n)
{
    int i = blockIdx.x * blockDim.x + threadIdx.x;
    float4 z = make_float4(0.f, 0.f, 0.f, 0.f);
    if (i < n4) { s0[i] = z; s1[i] = z; sf[i] = z; }
    if (i < n)  cnt[i] = 0.f;
}
__global__ void k_wt(const float* __restrict__ W1, const float* __restrict__ W2)
{
    int t = blockIdx.x * blockDim.x + threadIdx.x;
    if (t >= DD * DD) return;
    g_Wr1[t] = tf32r(W1[t]);
    g_Wr2[t] = tf32r(W2[t]);
}

// ---- init: lgX = tf32r(0.5*(x[c0]+x[c1])); scatter relu -> S0; cnt ---------
__global__ void k_init(const float* __restrict__ x,
                       const int* __restrict__ col0,
                       const int* __restrict__ col1, int E)
{
    int idx = blockIdx.x * blockDim.x + threadIdx.x;
    int e = idx >> 5, q = idx & 31;
    if (e >= E) return;
    int c0 = col0[e], c1 = col1[e];
    const float4* x4 = (const float4*)x;
    float4 a = x4[(size_t)c0 * DV + q];
    float4 b = x4[(size_t)c1 * DV + q];
    float4 r;
    r.x = 0.5f * (a.x + b.x);
    r.y = 0.5f * (a.y + b.y);
    r.z = 0.5f * (a.z + b.z);
    r.w = 0.5f * (a.w + b.w);
    if (c0 != c1) {
        float4 v;
        v.x = fmaxf(r.x + b.x, 0.f);
        v.y = fmaxf(r.y + b.y, 0.f);
        v.z = fmaxf(r.z + b.z, 0.f);
        v.w = fmaxf(r.w + b.w, 0.f);
        red_add_v4(&g_S0[(size_t)c1 * DD + 4 * q], v);
    }
    float4 rr;
    rr.x = tf32r(r.x); rr.y = tf32r(r.y); rr.z = tf32r(r.z); rr.w = tf32r(r.w);
    ((float4*)g_lgX)[(size_t)e * DV + q] = rr;
    if (q == 0) atomicAdd(&g_cnt[c1], 1.0f);
}

// ------------------- k_sw1: SW1 = tf32(S) @ W1 (N rows) ---------------------
#define SW1_SMEM ((128 * LDW + 128 * LDA) * 4)
__global__ void __launch_bounds__(256, 1)
k_sw1(const float* __restrict__ Sin, int N)
{
    extern __shared__ float sm[];
    float* sW = sm;                  // [128][LDW]
    float* sA = sm + 128 * LDW;      // [128][LDA]

    const int tid  = threadIdx.x;
    const int wid  = tid >> 5, lane = tid & 31;
    const int wm   = wid >> 1, wn = wid & 1;
    const int ty   = lane >> 2, tx4 = lane & 3;
    const int R0   = wm * 32;
    const int row0 = blockIdx.x * 128;

    #pragma unroll
    for (int i = tid; i < 4096; i += 256) {
        int k = i >> 5, n4 = i & 31;
        *(float4*)&sW[k * LDW + 4 * n4] = ((const float4*)g_Wr1)[i];
    }
    #pragma unroll
    for (int i = tid; i < 4096; i += 256) {
        int r = i >> 5, q = i & 31;
        int gr = row0 + r;
        float4 v = make_float4(0.f, 0.f, 0.f, 0.f);
        if (gr < N) {
            float4 s = ((const float4*)Sin)[(size_t)gr * DV + q];
            v.x = tf32r(s.x); v.y = tf32r(s.y);
            v.z = tf32r(s.z); v.w = tf32r(s.w);
        }
        *(float4*)&sA[r * LDA + 4 * q] = v;
    }
    __syncthreads();

    float acc[2][8][4];
    ZERO_ACC();
    const uint32_t* uA = (const uint32_t*)sA;
    const uint32_t* uW = (const uint32_t*)sW;
    GEMM_BODY(uW, uA, R0);
    __syncthreads();   // reads of sA done

    // acc -> sA rows R0.. in row-major, then coalesced v4 store
    {
        #pragma unroll
        for (int m = 0; m < 2; m++) {
            int rb = R0 + 16 * m + ty;
            #pragma unroll
            for (int n = 0; n < 8; n++) {
                int cc = wn * 64 + 8 * n + 2 * tx4;
                *(float2*)&sA[rb * LDA + cc] =
                    make_float2(acc[m][n][0], acc[m][n][1]);
                *(float2*)&sA[(rb + 8) * LDA + cc] =
                    make_float2(acc[m][n][2], acc[m][n][3]);
            }
        }
    }
    __syncthreads();
    {
        int r  = tid >> 1;              // 0..127
        int cb = (tid & 1) * 64;        // 64-word half per thread
        int gr = row0 + r;
        if (gr < N) {
            #pragma unroll
            for (int j = 0; j < 16; j++) {          // 16 x float4 = 64 words
                float4 o = *(float4*)&sA[r * LDA + cb + 4 * j];
                *(float4*)&g_SW1[(size_t)gr * DD + cb + 4 * j] = o;
            }
        }
    }
}

// ----------------- persistent fused MLP + message scatter -------------------
#define SW_WORDS (128 * LDW)
#define SA_WORDS (TILE * LDA)
#define SMEM_WORDS (2 * SW_WORDS + 256 + 4 * SA_WORDS)
#define SMEM_BYTES (SMEM_WORDS * 4)   // 207872 B

__global__ void __launch_bounds__(256, 1)
k_mlp(const int* __restrict__ col0, const int* __restrict__ col1,
      const float* __restrict__ x,
      const float* __restrict__ b1, const float* __restrict__ b2,
      float* __restrict__ Sout,
      int E, int final_mode, int ntiles, int tstride)
{
    extern __shared__ float sm[];
    float* sW1 = sm;
    float* sW2 = sm + SW_WORDS;
    float* sB1 = sm + 2 * SW_WORDS;        // [128]
    float* sB2 = sB1 + 128;                // [128]
    float* sAb = sB2 + 128;

    const int tid  = threadIdx.x;
    const int wid  = tid >> 5, lane = tid & 31;
    const int pid  = wid >> 1;                 // pair 0..3
    const int wn   = wid & 1;                  // column half within pair
    const int ty   = lane >> 2, tx4 = lane & 3;
    const int barid = 1 + pid;

    float* sA = sAb + pid * SA_WORDS;
    const uint32_t* uA  = (const uint32_t*)sA;
    const uint32_t* uW1 = (const uint32_t*)sW1;
    const uint32_t* uW2 = (const uint32_t*)sW2;
    const uint32_t sAu = smem_u32(sA);

    // row-phase role within the pair: 64 threads = 32 rows x 2 column halves
    const int t64   = wn * 32 + lane;
    const int srow  = t64 >> 1;            // 0..31
    const int cb    = (t64 & 1) * 64;      // word base of this thread's half
    const int wpart = (t64 & 1) * 16;      // float4 group base for staging

    // stage weights + biases once
    #pragma unroll
    for (int i = tid; i < 4096; i += 256) {
        int k = i >> 5, n4 = i & 31;
        *(float4*)&sW1[k * LDW + 4 * n4] = ((const float4*)g_Wr1)[i];
        *(float4*)&sW2[k * LDW + 4 * n4] = ((const float4*)g_Wr2)[i];
    }
    if (tid < 128) { sB1[tid] = b1[tid]; sB2[tid] = b2[tid]; }
    __syncthreads();

    int tile = blockIdx.x * 4 + pid;

    // prologue: stage first tile
    if (tile < ntiles) {
        int gr = tile * TILE + srow;
        if (gr < E) {
            const float* src = &g_lgX[(size_t)gr * DD + 4 * wpart];
            uint32_t dst = sAu + (srow * LDA + 4 * wpart) * 4;
            #pragma unroll
            for (int j = 0; j < 16; j++)
                cp_async16(dst + 16 * j, src + 4 * j);
        } else {
            float4 z = make_float4(0.f, 0.f, 0.f, 0.f);
            #pragma unroll
            for (int j = 0; j < 16; j++)
                *(float4*)&sA[srow * LDA + 4 * (wpart + j)] = z;
        }
        CP_COMMIT();
    }

    for (; tile < ntiles; tile += tstride) {
        const int row0 = tile * TILE;
        const int gr   = row0 + srow;         // this thread's row (row phase)
        const int myc0 = (gr < E) ? col0[gr] : 0;
        const int myc1 = (gr < E) ? col1[gr] : 0;

        CP_WAIT0();
        BAR(barid);

        float acc[2][8][4];
        ZERO_ACC();

        // ---------------- GEMM 1: O1 = lgX @ W1 ----------------
        GEMM_BODY(uW1, uA, 0);
        BAR(barid);            // sA reads done
        ACC_TO_SMEM(sA);       // O1 -> sA row-major
        BAR(barid);

        // row phase 1: T = tf32r(relu(O1 + SW1[col0] + b1)) -> sA in place
        if (gr < E) {
            const float* swp = &g_SW1[(size_t)myc0 * DD + cb];
            #pragma unroll
            for (int j = 0; j < 16; j++) {          // 16 x float4 = 64 words
                float4 swv = *(const float4*)&swp[4 * j];
                float4 ov  = *(float4*)&sA[srow * LDA + cb + 4 * j];
                float4 bb  = *(float4*)&sB1[cb + 4 * j];
                float4 t;
                t.x = tf32r(fmaxf(ov.x + swv.x + bb.x, 0.f));
                t.y = tf32r(fmaxf(ov.y + swv.y + bb.y, 0.f));
                t.z = tf32r(fmaxf(ov.z + swv.z + bb.z, 0.f));
                t.w = tf32r(fmaxf(ov.w + swv.w + bb.w, 0.f));
                *(float4*)&sA[srow * LDA + cb + 4 * j] = t;
            }
        }
        BAR(barid);

        ZERO_ACC();
        // ---------------- GEMM 2: O2 = T @ W2 ----------------
        GEMM_BODY(uW2, uA, 0);
        BAR(barid);            // sA reads done
        ACC_TO_SMEM(sA);       // O2 -> sA row-major
        BAR(barid);

        // pull own row-half into registers before sA is recycled
        float4 o[16];
        #pragma unroll
        for (int j = 0; j < 16; j++)
            o[j] = *(float4*)&sA[srow * LDA + cb + 4 * j];
        BAR(barid);            // all reads done -> buffer free

        // stage next tile (overlaps global epilogue)
        {
            int nt = tile + tstride;
            if (nt < ntiles) {
                int g2 = nt * TILE + srow;
                if (g2 < E) {
                    const float* src = &g_lgX[(size_t)g2 * DD + 4 * wpart];
                    uint32_t dst = sAu + (srow * LDA + 4 * wpart) * 4;
                    #pragma unroll
                    for (int j = 0; j < 16; j++)
                        cp_async16(dst + 16 * j, src + 4 * j);
                } else {
                    float4 z = make_float4(0.f, 0.f, 0.f, 0.f);
                    #pragma unroll
                    for (int j = 0; j < 16; j++)
                        *(float4*)&sA[srow * LDA + 4 * (wpart + j)] = z;
                }
                CP_COMMIT();
            }
        }

        // global epilogue: O = O2 + b2; write lgX tf32 (unless final); scatter
        if (gr < E) {
            bool emit = final_mode ? true : (myc0 != myc1);
            const float* xp = &x[(size_t)myc1 * DD + cb];
            float* sop = &Sout[(size_t)myc1 * DD + cb];
            #pragma unroll
            for (int j = 0; j < 16; j++) {
                float4 bb = *(float4*)&sB2[cb + 4 * j];
                float4 ov;
                ov.x = o[j].x + bb.x; ov.y = o[j].y + bb.y;
                ov.z = o[j].z + bb.z; ov.w = o[j].w + bb.w;
                if (!final_mode) {
                    float4 rr;
                    rr.x = tf32r(ov.x); rr.y = tf32r(ov.y);
                    rr.z = tf32r(ov.z); rr.w = tf32r(ov.w);
                    *(float4*)&g_lgX[(size_t)gr * DD + cb + 4 * j] = rr;
                    if (emit) {
                        float4 xs = *(const float4*)&xp[4 * j];
                        float4 v;
                        v.x = fmaxf(ov.x + xs.x, 0.f);
                        v.y = fmaxf(ov.y + xs.y, 0.f);
                        v.z = fmaxf(ov.z + xs.z, 0.f);
                        v.w = fmaxf(ov.w + xs.w, 0.f);
                        red_add_v4(&sop[4 * j], v);
                    }
                } else {
                    red_add_v4(&sop[4 * j], ov);
                }
            }
        }
    }
}

// ----------------------- out = x + relu(Sf/cnt or 0) ------------------------
__global__ void k_fout(const float* __restrict__ x, float* __restrict__ out, int N)
{
    int idx = blockIdx.x * blockDim.x + threadIdx.x;
    int v = idx >> 5, q = idx & 31;
    if (v >= N) return;
    float c   = g_cnt[v];
    float inv = (c > 0.f) ? (1.f / c) : 0.f;
    float4 s  = ((const float4*)g_Sf)[(size_t)v * DV + q];
    float4 xv = ((const float4*)x)[(size_t)v * DV + q];
    float4 o;
    o.x = xv.x + fmaxf(s.x * inv, 0.f);
    o.y = xv.y + fmaxf(s.y * inv, 0.f);
    o.z = xv.z + fmaxf(s.z * inv, 0.f);
    o.w = xv.w + fmaxf(s.w * inv, 0.f);
    ((float4*)out)[(size_t)v * DV + q] = o;
}

// ---------------------------------------------------------------------------
extern "C" void kernel_launch(void* const* d_in, const int* in_sizes, int n_in,
                              void* d_out, int out_size)
{
    const float* x    = (const float*)d_in[0];
    const float* W1   = (const float*)d_in[1];
    const float* b1   = (const float*)d_in[2];
    const float* W2   = (const float*)d_in[3];
    const float* b2   = (const float*)d_in[4];
    const int*   col0 = (const int*)d_in[5];
    const int*   col1 = (const int*)d_in[6];
    // lg_src / lg_dst / edge_attr_idx are algebraically redundant.

    const int E = in_sizes[5];
    const int N = in_sizes[0] / DD;
    float* out = (float*)d_out;

    void *pS0, *pS1, *pSf, *pC;
    cudaGetSymbolAddress(&pS0, g_S0);
    cudaGetSymbolAddress(&pS1, g_S1);
    cudaGetSymbolAddress(&pSf, g_Sf);
    cudaGetSymbolAddress(&pC,  g_cnt);

    cudaFuncSetAttribute((const void*)k_mlp,
                         cudaFuncAttributeMaxDynamicSharedMemorySize, SMEM_BYTES);
    cudaFuncSetAttribute((const void*)k_sw1,
                         cudaFuncAttributeMaxDynamicSharedMemorySize, SW1_SMEM);

    int smcount = 148;
    cudaDeviceGetAttribute(&smcount, cudaDevAttrMultiProcessorCount, 0);

    const int tpb = 256;
    const int nbE = (E * 32 + tpb - 1) / tpb;
    const int nbN = (N * 32 + tpb - 1) / tpb;
    const int nbS = (N + 127) / 128;
    const int ntiles  = (E + TILE - 1) / TILE;
    const int tstride = 4 * smcount;

    k_zero<<<(N * 32 + tpb - 1) / tpb, tpb>>>((float4*)pS0, (float4*)pS1,
                                              (float4*)pSf, (float*)pC,
                                              N * 32, N);
    k_wt<<<(DD * DD + tpb - 1) / tpb, tpb>>>(W1, W2);
    k_init<<<nbE, tpb>>>(x, col0, col1, E);

    k_sw1<<<nbS, tpb, SW1_SMEM>>>((const float*)pS0, N);
    k_mlp<<<smcount, tpb, SMEM_BYTES>>>(col0, col1, x, b1, b2,
                                        (float*)pS1, E, 0, ntiles, tstride);
    k_sw1<<<nbS, tpb, SW1_SMEM>>>((const float*)pS1, N);
    k_mlp<<<smcount, tpb, SMEM_BYTES>>>(col0, col1, x, b1, b2,
                                        (float*)pSf, E, 1, ntiles, tstride);
    k_fout<<<nbN, tpb>>>(x, out, N);
}

// round 8
// speedup vs baseline: 1.0895x; 1.0895x over previous
#include <cuda_runtime.h>
#include <cstdint>

// ---------------------------------------------------------------------------
// LGNN GINE layer, algebraically collapsed + linearity-split tf32 MMA MLP.
//   lgX  = 0.5*(x[col0]+x[col1])                          (stored tf32-rounded)
//   2x:  S[v]  = sum_{i: col1[i]==v, col0[i]!=col1[i]} relu(lgX[i]+x[v])
//        SW1   = tf32(S) @ W1                             (separate small GEMM)
//        lgX   = relu(lgX@W1 + SW1[col0] + b1) @ W2 + b2
//   out  = x + relu( segment_mean(lgX, col1) )
// k_mlp v3: persistent, 8 fully INDEPENDENT warps, 16-row tiles, zero block
// barriers in the main loop (only __syncwarp). Private swizzled A per warp.
// ---------------------------------------------------------------------------

#define DD   128
#define DV   32
#define MAXE 200000
#define MAXN 50000
#define TILE 16

__device__ float g_S0[(size_t)MAXN * DD];
__device__ float g_S1[(size_t)MAXN * DD];
__device__ float g_Sf[(size_t)MAXN * DD];
__device__ float g_SW1[(size_t)MAXN * DD];
__device__ float g_lgX[(size_t)MAXE * DD];
__device__ float g_cnt[MAXN];
__device__ float g_Wr1[DD * DD];   // W1 tf32-rounded, [k][n]
__device__ float g_Wr2[DD * DD];

// ----------------------------- helpers --------------------------------------
__device__ __forceinline__ uint32_t smem_u32(const void* p) {
    uint32_t a;
    asm("{ .reg .u64 t; cvta.to.shared.u64 t, %1; cvt.u32.u64 %0, t; }"
        : "=r"(a) : "l"(p));
    return a;
}
__device__ __forceinline__ float tf32r(float f) {
    uint32_t u;
    asm("cvt.rna.tf32.f32 %0, %1;" : "=r"(u) : "f"(f));
    return __uint_as_float(u);
}
__device__ __forceinline__ void red_add_v4(float* p, float4 v) {
    asm volatile("red.global.add.v4.f32 [%0], {%1,%2,%3,%4};"
                 :: "l"(p), "f"(v.x), "f"(v.y), "f"(v.z), "f"(v.w) : "memory");
}
__device__ __forceinline__ void mma_tf32(float* d, uint32_t a0, uint32_t a1,
                                         uint32_t a2, uint32_t a3,
                                         uint32_t b0, uint32_t b1) {
    asm volatile(
        "mma.sync.aligned.m16n8k8.row.col.f32.tf32.tf32.f32 "
        "{%0,%1,%2,%3}, {%4,%5,%6,%7}, {%8,%9}, {%0,%1,%2,%3};"
        : "+f"(d[0]), "+f"(d[1]), "+f"(d[2]), "+f"(d[3])
        : "r"(a0), "r"(a1), "r"(a2), "r"(a3), "r"(b0), "r"(b1));
}
__device__ __forceinline__ void cp_async16(uint32_t dst, const void* src) {
    asm volatile("cp.async.cg.shared.global [%0], [%1], 16;"
                 :: "r"(dst), "l"(src) : "memory");
}
#define CP_COMMIT() asm volatile("cp.async.commit_group;" ::: "memory")
#define CP_WAIT0()  asm volatile("cp.async.wait_group 0;"  ::: "memory")

#define LDW 136
// float4-granular XOR swizzle for A: row r, float4-col c4 (0..31), word ofs o
#define SWA(r, c4, o) (((r) << 7) + (((((c4) ^ ((r) & 7))) << 2) | (o)))

// ------------------- zero scratch + weight rounding --------------------------
__global__ void k_zero(float4* s0, float4* s1, float4* sf, float* cnt,
                       int n4, int n)
{
    int i = blockIdx.x * blockDim.x + threadIdx.x;
    float4 z = make_float4(0.f, 0.f, 0.f, 0.f);
    if (i < n4) { s0[i] = z; s1[i] = z; sf[i] = z; }
    if (i < n)  cnt[i] = 0.f;
}
__global__ void k_wt(const float* __restrict__ W1, const float* __restrict__ W2)
{
    int t = blockIdx.x * blockDim.x + threadIdx.x;
    if (t >= DD * DD) return;
    g_Wr1[t] = tf32r(W1[t]);
    g_Wr2[t] = tf32r(W2[t]);
}

// ---- init: lgX = tf32r(0.5*(x[c0]+x[c1])); scatter relu -> S0; cnt ---------
__global__ void k_init(const float* __restrict__ x,
                       const int* __restrict__ col0,
                       const int* __restrict__ col1, int E)
{
    int idx = blockIdx.x * blockDim.x + threadIdx.x;
    int e = idx >> 5, q = idx & 31;
    if (e >= E) return;
    int c0 = col0[e], c1 = col1[e];
    const float4* x4 = (const float4*)x;
    float4 a = x4[(size_t)c0 * DV + q];
    float4 b = x4[(size_t)c1 * DV + q];
    float4 r;
    r.x = 0.5f * (a.x + b.x);
    r.y = 0.5f * (a.y + b.y);
    r.z = 0.5f * (a.z + b.z);
    r.w = 0.5f * (a.w + b.w);
    if (c0 != c1) {
        float4 v;
        v.x = fmaxf(r.x + b.x, 0.f);
        v.y = fmaxf(r.y + b.y, 0.f);
        v.z = fmaxf(r.z + b.z, 0.f);
        v.w = fmaxf(r.w + b.w, 0.f);
        red_add_v4(&g_S0[(size_t)c1 * DD + 4 * q], v);
    }
    float4 rr;
    rr.x = tf32r(r.x); rr.y = tf32r(r.y); rr.z = tf32r(r.z); rr.w = tf32r(r.w);
    ((float4*)g_lgX)[(size_t)e * DV + q] = rr;
    if (q == 0) atomicAdd(&g_cnt[c1], 1.0f);
}

// ------------------- k_sw1: SW1 = tf32(S) @ W1 (N rows) ---------------------
// (unchanged from R7 — 128-row CTA tiles, pair warps, validated)
#define LDA5 132
#define SW1_SMEM ((128 * LDW + 128 * LDA5) * 4)
__global__ void __launch_bounds__(256, 1)
k_sw1(const float* __restrict__ Sin, int N)
{
    extern __shared__ float sm[];
    float* sW = sm;                  // [128][LDW]
    float* sA = sm + 128 * LDW;      // [128][LDA5]

    const int tid  = threadIdx.x;
    const int wid  = tid >> 5, lane = tid & 31;
    const int wm   = wid >> 1, wn = wid & 1;
    const int ty   = lane >> 2, tx4 = lane & 3;
    const int R0   = wm * 32;
    const int row0 = blockIdx.x * 128;

    #pragma unroll
    for (int i = tid; i < 4096; i += 256) {
        int k = i >> 5, n4 = i & 31;
        *(float4*)&sW[k * LDW + 4 * n4] = ((const float4*)g_Wr1)[i];
    }
    #pragma unroll
    for (int i = tid; i < 4096; i += 256) {
        int r = i >> 5, q = i & 31;
        int gr = row0 + r;
        float4 v = make_float4(0.f, 0.f, 0.f, 0.f);
        if (gr < N) {
            float4 s = ((const float4*)Sin)[(size_t)gr * DV + q];
            v.x = tf32r(s.x); v.y = tf32r(s.y);
            v.z = tf32r(s.z); v.w = tf32r(s.w);
        }
        *(float4*)&sA[r * LDA5 + 4 * q] = v;
    }
    __syncthreads();

    float acc[2][8][4];
    #pragma unroll
    for (int m = 0; m < 2; m++)
        #pragma unroll
        for (int n = 0; n < 8; n++)
            #pragma unroll
            for (int j = 0; j < 4; j++) acc[m][n][j] = 0.f;

    const uint32_t* uA = (const uint32_t*)sA;
    const uint32_t* uW = (const uint32_t*)sW;
    #pragma unroll
    for (int kk = 0; kk < 16; kk++) {
        uint32_t a[2][4], b[8][2];
        #pragma unroll
        for (int m = 0; m < 2; m++) {
            int rb = R0 + 16 * m;
            a[m][0] = uA[(rb + ty) * LDA5 + kk * 8 + tx4];
            a[m][1] = uA[(rb + ty + 8) * LDA5 + kk * 8 + tx4];
            a[m][2] = uA[(rb + ty) * LDA5 + kk * 8 + tx4 + 4];
            a[m][3] = uA[(rb + ty + 8) * LDA5 + kk * 8 + tx4 + 4];
        }
        #pragma unroll
        for (int n = 0; n < 8; n++) {
            int cc = wn * 64 + 8 * n + ty;
            b[n][0] = uW[(kk * 8 + tx4) * LDW + cc];
            b[n][1] = uW[(kk * 8 + tx4 + 4) * LDW + cc];
        }
        #pragma unroll
        for (int m = 0; m < 2; m++)
            #pragma unroll
            for (int n = 0; n < 8; n++)
                mma_tf32(acc[m][n], a[m][0], a[m][1], a[m][2], a[m][3],
                         b[n][0], b[n][1]);
    }
    __syncthreads();

    #pragma unroll
    for (int m = 0; m < 2; m++) {
        int rb = R0 + 16 * m + ty;
        #pragma unroll
        for (int n = 0; n < 8; n++) {
            int cc = wn * 64 + 8 * n + 2 * tx4;
            *(float2*)&sA[rb * LDA5 + cc] =
                make_float2(acc[m][n][0], acc[m][n][1]);
            *(float2*)&sA[(rb + 8) * LDA5 + cc] =
                make_float2(acc[m][n][2], acc[m][n][3]);
        }
    }
    __syncthreads();
    {
        int r  = tid >> 1;
        int cb = (tid & 1) * 64;
        int gr = row0 + r;
        if (gr < N) {
            #pragma unroll
            for (int j = 0; j < 16; j++) {
                float4 o = *(float4*)&sA[r * LDA5 + cb + 4 * j];
                *(float4*)&g_SW1[(size_t)gr * DD + cb + 4 * j] = o;
            }
        }
    }
}

// ----------------- persistent fused MLP: warp-independent -------------------
#define SW_WORDS (128 * LDW)
#define SA_WORDS (TILE * 128)               // 2048 words per warp
#define SMEM_WORDS (2 * SW_WORDS + 8 * SA_WORDS)
#define SMEM_BYTES (SMEM_WORDS * 4)         // 204800 B

__global__ void __launch_bounds__(256, 1)
k_mlp(const int* __restrict__ col0, const int* __restrict__ col1,
      const float* __restrict__ x,
      const float* __restrict__ b1, const float* __restrict__ b2,
      float* __restrict__ Sout,
      int E, int final_mode, int ntiles, int tstride)
{
    extern __shared__ float sm[];
    float* sW1 = sm;
    float* sW2 = sm + SW_WORDS;
    float* sAb = sm + 2 * SW_WORDS;

    const int tid  = threadIdx.x;
    const int wid  = tid >> 5, lane = tid & 31;
    const int ty   = lane >> 2, tx4 = lane & 3;   // fragment coords
    const int srow = lane >> 1;                   // row-phase row (0..15)
    const int hb   = lane & 1;                    // row-phase half (64 words)

    float* sA = sAb + wid * SA_WORDS;
    const uint32_t* uA  = (const uint32_t*)sA;
    const uint32_t* uW1 = (const uint32_t*)sW1;
    const uint32_t* uW2 = (const uint32_t*)sW2;
    const uint32_t sAu = smem_u32(sA);

    // stage weights once (block-wide, single sync)
    #pragma unroll
    for (int i = tid; i < 4096; i += 256) {
        int k = i >> 5, n4 = i & 31;
        *(float4*)&sW1[k * LDW + 4 * n4] = ((const float4*)g_Wr1)[i];
        *(float4*)&sW2[k * LDW + 4 * n4] = ((const float4*)g_Wr2)[i];
    }
    __syncthreads();

    // biases resident in registers: cols 8n+2tx4, 8n+2tx4+1 per lane
    float2 rb1[16], rb2[16];
    #pragma unroll
    for (int n = 0; n < 16; n++) {
        rb1[n] = *(const float2*)&b1[8 * n + 2 * tx4];
        rb2[n] = *(const float2*)&b2[8 * n + 2 * tx4];
    }

    int tile = blockIdx.x * 8 + wid;

    // prologue: stage first tile (cp.async, swizzled dst)
    if (tile < ntiles) {
        int gr = tile * TILE + srow;
        if (gr >= E) gr = E - 1;
        const float* src = &g_lgX[(size_t)gr * DD + hb * 64];
        #pragma unroll
        for (int u = 0; u < 16; u++)
            cp_async16(sAu + 4 * SWA(srow, hb * 16 + u, 0), src + 4 * u);
        CP_COMMIT();
    }

    for (; tile < ntiles; tile += tstride) {
        const int row0 = tile * TILE;
        // per-fragment-row indices (epilogue 1)
        int ra = row0 + ty, rbq = row0 + ty + 8;
        int c0a = col0[ra < E ? ra : E - 1];
        int c0b = col0[rbq < E ? rbq : E - 1];
        // row-phase indices (epilogue 2)
        int grr = row0 + srow;
        int myc0 = col0[grr < E ? grr : E - 1];
        int myc1 = col1[grr < E ? grr : E - 1];

        CP_WAIT0();
        __syncwarp();

        float acc[16][4];
        #pragma unroll
        for (int n = 0; n < 16; n++)
            #pragma unroll
            for (int j = 0; j < 4; j++) acc[n][j] = 0.f;

        // ---------------- GEMM 1: O1 = lgX @ W1 ----------------
        #pragma unroll 4
        for (int kk = 0; kk < 16; kk++) {
            uint32_t a0 = uA[SWA(ty,     kk * 2,     tx4)];
            uint32_t a1 = uA[SWA(ty + 8, kk * 2,     tx4)];
            uint32_t a2 = uA[SWA(ty,     kk * 2 + 1, tx4)];
            uint32_t a3 = uA[SWA(ty + 8, kk * 2 + 1, tx4)];
            #pragma unroll
            for (int n = 0; n < 16; n++) {
                uint32_t b0 = uW1[(kk * 8 + tx4)     * LDW + 8 * n + ty];
                uint32_t b1r = uW1[(kk * 8 + tx4 + 4) * LDW + 8 * n + ty];
                mma_tf32(acc[n], a0, a1, a2, a3, b0, b1r);
            }
        }
        __syncwarp();

        // epilogue 1 (fragment-direct): T = tf32r(relu(O1 + SW1[col0] + b1))
        {
            const float* swa = &g_SW1[(size_t)c0a * DD];
            const float* swb = &g_SW1[(size_t)c0b * DD];
            #pragma unroll
            for (int n = 0; n < 16; n++) {
                int cc = 8 * n + 2 * tx4;
                float2 s0 = *(const float2*)&swa[cc];
                float2 s1 = *(const float2*)&swb[cc];
                float2 t0, t1;
                t0.x = tf32r(fmaxf(acc[n][0] + s0.x + rb1[n].x, 0.f));
                t0.y = tf32r(fmaxf(acc[n][1] + s0.y + rb1[n].y, 0.f));
                t1.x = tf32r(fmaxf(acc[n][2] + s1.x + rb1[n].x, 0.f));
                t1.y = tf32r(fmaxf(acc[n][3] + s1.y + rb1[n].y, 0.f));
                int c4 = 2 * n + (tx4 >> 1), o = (2 * tx4) & 3;
                *(float2*)&sA[SWA(ty,     c4, o)] = t0;
                *(float2*)&sA[SWA(ty + 8, c4, o)] = t1;
                acc[n][0] = 0.f; acc[n][1] = 0.f;
                acc[n][2] = 0.f; acc[n][3] = 0.f;
            }
        }
        __syncwarp();

        // ---------------- GEMM 2: O2 = T @ W2 ----------------
        #pragma unroll 4
        for (int kk = 0; kk < 16; kk++) {
            uint32_t a0 = uA[SWA(ty,     kk * 2,     tx4)];
            uint32_t a1 = uA[SWA(ty + 8, kk * 2,     tx4)];
            uint32_t a2 = uA[SWA(ty,     kk * 2 + 1, tx4)];
            uint32_t a3 = uA[SWA(ty + 8, kk * 2 + 1, tx4)];
            #pragma unroll
            for (int n = 0; n < 16; n++) {
                uint32_t b0 = uW2[(kk * 8 + tx4)     * LDW + 8 * n + ty];
                uint32_t b1r = uW2[(kk * 8 + tx4 + 4) * LDW + 8 * n + ty];
                mma_tf32(acc[n], a0, a1, a2, a3, b0, b1r);
            }
        }
        __syncwarp();

        // O2 + b2 -> sA (row-major, unrounded)
        #pragma unroll
        for (int n = 0; n < 16; n++) {
            int c4 = 2 * n + (tx4 >> 1), o = (2 * tx4) & 3;
            *(float2*)&sA[SWA(ty, c4, o)] =
                make_float2(acc[n][0] + rb2[n].x, acc[n][1] + rb2[n].y);
            *(float2*)&sA[SWA(ty + 8, c4, o)] =
                make_float2(acc[n][2] + rb2[n].x, acc[n][3] + rb2[n].y);
        }
        __syncwarp();

        // pull own row-half into registers
        float4 o[16];
        #pragma unroll
        for (int j = 0; j < 16; j++)
            o[j] = *(float4*)&sA[SWA(srow, hb * 16 + j, 0)];
        __syncwarp();

        // stage next tile (overlaps global epilogue)
        {
            int nt = tile + tstride;
            if (nt < ntiles) {
                int g2 = nt * TILE + srow;
                if (g2 >= E) g2 = E - 1;
                const float* src = &g_lgX[(size_t)g2 * DD + hb * 64];
                #pragma unroll
                for (int u = 0; u < 16; u++)
                    cp_async16(sAu + 4 * SWA(srow, hb * 16 + u, 0), src + 4 * u);
                CP_COMMIT();
            }
        }

        // global epilogue: write lgX tf32 (unless final); fused scatter
        if (grr < E) {
            bool emit = final_mode ? true : (myc0 != myc1);
            const float* xp  = &x[(size_t)myc1 * DD + hb * 64];
            float* sop = &Sout[(size_t)myc1 * DD + hb * 64];
            float* lxp = &g_lgX[(size_t)grr * DD + hb * 64];
            #pragma unroll
            for (int j = 0; j < 16; j++) {
                float4 ov = o[j];
                if (!final_mode) {
                    float4 rr;
                    rr.x = tf32r(ov.x); rr.y = tf32r(ov.y);
                    rr.z = tf32r(ov.z); rr.w = tf32r(ov.w);
                    *(float4*)&lxp[4 * j] = rr;
                    if (emit) {
                        float4 xs = *(const float4*)&xp[4 * j];
                        float4 v;
                        v.x = fmaxf(ov.x + xs.x, 0.f);
                        v.y = fmaxf(ov.y + xs.y, 0.f);
                        v.z = fmaxf(ov.z + xs.z, 0.f);
                        v.w = fmaxf(ov.w + xs.w, 0.f);
                        red_add_v4(&sop[4 * j], v);
                    }
                } else {
                    red_add_v4(&sop[4 * j], ov);
                }
            }
        }
    }
}

// ----------------------- out = x + relu(Sf/cnt or 0) ------------------------
__global__ void k_fout(const float* __restrict__ x, float* __restrict__ out, int N)
{
    int idx = blockIdx.x * blockDim.x + threadIdx.x;
    int v = idx >> 5, q = idx & 31;
    if (v >= N) return;
    float c   = g_cnt[v];
    float inv = (c > 0.f) ? (1.f / c) : 0.f;
    float4 s  = ((const float4*)g_Sf)[(size_t)v * DV + q];
    float4 xv = ((const float4*)x)[(size_t)v * DV + q];
    float4 o;
    o.x = xv.x + fmaxf(s.x * inv, 0.f);
    o.y = xv.y + fmaxf(s.y * inv, 0.f);
    o.z = xv.z + fmaxf(s.z * inv, 0.f);
    o.w = xv.w + fmaxf(s.w * inv, 0.f);
    ((float4*)out)[(size_t)v * DV + q] = o;
}

// ---------------------------------------------------------------------------
extern "C" void kernel_launch(void* const* d_in, const int* in_sizes, int n_in,
                              void* d_out, int out_size)
{
    const float* x    = (const float*)d_in[0];
    const float* W1   = (const float*)d_in[1];
    const float* b1   = (const float*)d_in[2];
    const float* W2   = (const float*)d_in[3];
    const float* b2   = (const float*)d_in[4];
    const int*   col0 = (const int*)d_in[5];
    const int*   col1 = (const int*)d_in[6];
    // lg_src / lg_dst / edge_attr_idx are algebraically redundant.

    const int E = in_sizes[5];
    const int N = in_sizes[0] / DD;
    float* out = (float*)d_out;

    void *pS0, *pS1, *pSf, *pC;
    cudaGetSymbolAddress(&pS0, g_S0);
    cudaGetSymbolAddress(&pS1, g_S1);
    cudaGetSymbolAddress(&pSf, g_Sf);
    cudaGetSymbolAddress(&pC,  g_cnt);

    cudaFuncSetAttribute((const void*)k_mlp,
                         cudaFuncAttributeMaxDynamicSharedMemorySize, SMEM_BYTES);
    cudaFuncSetAttribute((const void*)k_sw1,
                         cudaFuncAttributeMaxDynamicSharedMemorySize, SW1_SMEM);

    int smcount = 148;
    cudaDeviceGetAttribute(&smcount, cudaDevAttrMultiProcessorCount, 0);

    const int tpb = 256;
    const int nbE = (E * 32 + tpb - 1) / tpb;
    const int nbN = (N * 32 + tpb - 1) / tpb;
    const int nbS = (N + 127) / 128;
    const int ntiles  = (E + TILE - 1) / TILE;
    const int tstride = 8 * smcount;

    k_zero<<<(N * 32 + tpb - 1) / tpb, tpb>>>((float4*)pS0, (float4*)pS1,
                                              (float4*)pSf, (float*)pC,
                                              N * 32, N);
    k_wt<<<(DD * DD + tpb - 1) / tpb, tpb>>>(W1, W2);
    k_init<<<nbE, tpb>>>(x, col0, col1, E);

    k_sw1<<<nbS, tpb, SW1_SMEM>>>((const float*)pS0, N);
    k_mlp<<<smcount, tpb, SMEM_BYTES>>>(col0, col1, x, b1, b2,
                                        (float*)pS1, E, 0, ntiles, tstride);
    k_sw1<<<nbS, tpb, SW1_SMEM>>>((const float*)pS1, N);
    k_mlp<<<smcount, tpb, SMEM_BYTES>>>(col0, col1, x, b1, b2,
                                        (float*)pSf, E, 1, ntiles, tstride);
    k_fout<<<nbN, tpb>>>(x, out, N);
}